// round 4
// baseline (speedup 1.0000x reference)
#include <cuda_runtime.h>
#include <cuda_fp16.h>
#include <cstdint>
#include <cstddef>

#define TPB     256
#define MB      16          // batch rows per CTA
#define TSTEPS  512
#define HID     128
#define G4      512         // 4*H
#define ISZ     5
#define KTOT    134         // 128 h-rows + 5 x-rows + 1 ones/bias row
#define WROW    512         // halfs per W row (gate dim)
#define HROW    KTOT        // ull (f32x2) entries per H row

#define W_BYTES  (KTOT * WROW * 2)        // 137216
#define H_OFFB   W_BYTES
#define H_BYTES  (MB * HROW * 8)          // 17152
#define SMEM_TOTAL (W_BYTES + H_BYTES)    // 154368 < 228KB

__device__ __forceinline__ unsigned long long pack2(float x, float y) {
    unsigned long long r;
    asm("mov.b64 %0, {%1, %2};" : "=l"(r)
        : "r"(__float_as_uint(x)), "r"(__float_as_uint(y)));
    return r;
}
__device__ __forceinline__ float2 unpack2(unsigned long long v) {
    unsigned a, b;
    asm("mov.b64 {%0, %1}, %2;" : "=r"(a), "=r"(b) : "l"(v));
    return make_float2(__uint_as_float(a), __uint_as_float(b));
}
// Packed fp32x2 FMA (Blackwell FFMA2) — full fp32 precision per lane.
__device__ __forceinline__ void fma2(unsigned long long& d,
                                     unsigned long long a,
                                     unsigned long long b) {
    asm("fma.rn.f32x2 %0, %1, %2, %0;" : "+l"(d) : "l"(a), "l"(b));
}
__device__ __forceinline__ float sigf(float x) {
    float e = __expf(-x);
    return __fdividef(1.0f, 1.0f + e);
}
__device__ __forceinline__ float tanhf_fast(float x) {
    float e = __expf(-2.0f * x);
    return __fdividef(1.0f - e, 1.0f + e);
}

__global__ void __launch_bounds__(TPB, 1)
lstm_persist(const float* __restrict__ x,     const float* __restrict__ W_ih,
             const float* __restrict__ W_hh,  const float* __restrict__ b_ih,
             const float* __restrict__ b_hh,  const float* __restrict__ W_lin,
             const float* __restrict__ b_lin, float* __restrict__ out)
{
    extern __shared__ char smem[];
    __half* Wsm = reinterpret_cast<__half*>(smem);                       // [KTOT][512] fp16
    unsigned long long* Hsm =
        reinterpret_cast<unsigned long long*>(smem + H_OFFB);            // [MB][KTOT] (h,h) f32x2

    const int tid = threadIdx.x;
    const int cg  = tid & 63;        // 64 column groups (hidden pair j0 = 2*cg)
    const int rg  = tid >> 6;        // 4 row groups (rows r0..r0+3)
    const int r0  = rg << 2;
    const int j0  = cg << 1;
    const int b0  = blockIdx.x * MB;

    // ---- one-time staging: W_hh (transposed, fp16), W_ih rows, bias row ----
    for (int e = tid; e < G4 * HID; e += TPB) {
        int n = e >> 7, k = e & (HID - 1);
        Wsm[k * WROW + n] = __float2half(W_hh[e]);          // W_hh[n][k] -> Wsm[k][n]
    }
    for (int e = tid; e < G4 * ISZ; e += TPB) {
        int n = e / ISZ, i = e - n * ISZ;
        Wsm[(HID + i) * WROW + n] = __float2half(W_ih[e]);  // x-projection rows
    }
    for (int e = tid; e < G4; e += TPB)
        Wsm[(KTOT - 1) * WROW + e] = __float2half(b_ih[e] + b_hh[e]);  // bias row

    // ---- init H: h=0 rows, ones row (bias), x(t=0) rows ----
    for (int e = tid; e < MB * HID; e += TPB) {
        int r = e >> 7, k = e & (HID - 1);
        Hsm[r * HROW + k] = 0ull;
    }
    if (tid < MB) Hsm[tid * HROW + (KTOT - 1)] = pack2(1.0f, 1.0f);
    if (tid < MB * ISZ) {
        int r = tid / ISZ, i = tid - r * ISZ;
        float v = x[(size_t)(b0 + r) * (TSTEPS * ISZ) + i];
        Hsm[r * HROW + HID + i] = pack2(v, v);
    }

    float c_st[4][2];
    #pragma unroll
    for (int a = 0; a < 4; a++) { c_st[a][0] = 0.f; c_st[a][1] = 0.f; }

    __syncthreads();

    for (int t = 0; t < TSTEPS; t++) {
        // acc[a][g] : f32x2 over hidden pair (j0, j0+1), gate g, row r0+a
        unsigned long long acc[4][4];
        #pragma unroll
        for (int a = 0; a < 4; a++) {
            #pragma unroll
            for (int g = 0; g < 4; g++) acc[a][g] = 0ull;
        }

        // gates = bias + x@W_ih + h@W_hh, all folded into one K loop
        #pragma unroll 4
        for (int k = 0; k < KTOT; k += 2) {
            ulonglong2 hv[4];
            #pragma unroll
            for (int a = 0; a < 4; a++)   // warp-uniform broadcast LDS.128 (2 k-slices)
                hv[a] = *reinterpret_cast<const ulonglong2*>(&Hsm[(r0 + a) * HROW + k]);
            unsigned long long wb0[4], wb1[4];
            #pragma unroll
            for (int g = 0; g < 4; g++) { // conflict-free half2 loads
                float2 w0 = __half22float2(
                    *reinterpret_cast<const __half2*>(&Wsm[k * WROW + (g << 7) + j0]));
                float2 w1 = __half22float2(
                    *reinterpret_cast<const __half2*>(&Wsm[(k + 1) * WROW + (g << 7) + j0]));
                wb0[g] = pack2(w0.x, w0.y);
                wb1[g] = pack2(w1.x, w1.y);
            }
            #pragma unroll
            for (int a = 0; a < 4; a++) {
                #pragma unroll
                for (int g = 0; g < 4; g++) {
                    fma2(acc[a][g], hv[a].x, wb0[g]);   // 16 independent FFMA2 chains
                    fma2(acc[a][g], hv[a].y, wb1[g]);
                }
            }
        }
        __syncthreads();   // all reads of old h / x done

        // prefetch x(t+1) early (DRAM latency hidden behind activations)
        float xnv = 0.f; int xr = 0, xi = 0;
        const bool do_x = (tid < MB * ISZ) && (t + 1 < TSTEPS);
        if (do_x) {
            xr = tid / ISZ; xi = tid - xr * ISZ;
            xnv = x[(size_t)(b0 + xr) * (TSTEPS * ISZ) + (size_t)(t + 1) * ISZ + xi];
        }

        // activations: thread-local (c in registers), conflict-free STS.128 of (h,h) pairs
        #pragma unroll
        for (int a = 0; a < 4; a++) {
            float2 gi = unpack2(acc[a][0]);
            float2 gf = unpack2(acc[a][1]);
            float2 gg = unpack2(acc[a][2]);
            float2 go = unpack2(acc[a][3]);
            float c0 = sigf(gf.x) * c_st[a][0] + sigf(gi.x) * tanhf_fast(gg.x);
            float c1 = sigf(gf.y) * c_st[a][1] + sigf(gi.y) * tanhf_fast(gg.y);
            c_st[a][0] = c0; c_st[a][1] = c1;
            float h0 = sigf(go.x) * tanhf_fast(c0);
            float h1 = sigf(go.y) * tanhf_fast(c1);
            ulonglong2 hw;
            hw.x = pack2(h0, h0);
            hw.y = pack2(h1, h1);
            *reinterpret_cast<ulonglong2*>(&Hsm[(r0 + a) * HROW + j0]) = hw;
        }

        if (do_x) Hsm[xr * HROW + HID + xi] = pack2(xnv, xnv);

        __syncthreads();   // new h / x visible for next step
    }

    // ---- epilogue: out[b] = h_n . W_lin + b_lin ----
    if (tid < 128) {
        const int row = tid >> 3, seg = tid & 7;   // 8 threads per batch row
        float s = 0.f;
        #pragma unroll
        for (int jj = 0; jj < 16; jj++) {
            int j = (seg << 4) + jj;
            s += unpack2(Hsm[row * HROW + j]).x * W_lin[j];
        }
        s += __shfl_xor_sync(0xffffffffu, s, 4);
        s += __shfl_xor_sync(0xffffffffu, s, 2);
        s += __shfl_xor_sync(0xffffffffu, s, 1);
        if (seg == 0) out[b0 + row] = s + b_lin[0];
    }
}

extern "C" void kernel_launch(void* const* d_in, const int* in_sizes, int n_in,
                              void* d_out, int out_size) {
    const float* x     = (const float*)d_in[0];
    const float* W_ih  = (const float*)d_in[1];
    const float* W_hh  = (const float*)d_in[2];
    const float* b_ih  = (const float*)d_in[3];
    const float* b_hh  = (const float*)d_in[4];
    const float* W_lin = (const float*)d_in[5];
    const float* b_lin = (const float*)d_in[6];
    float* out = (float*)d_out;

    int B    = in_sizes[0] / (TSTEPS * ISZ);   // 2048
    int nCTA = B / MB;                          // 128 CTAs -> one wave on 148 SMs

    cudaFuncSetAttribute(lstm_persist,
                         cudaFuncAttributeMaxDynamicSharedMemorySize, SMEM_TOTAL);
    lstm_persist<<<nCTA, TPB, SMEM_TOTAL>>>(x, W_ih, W_hh, b_ih, b_hh,
                                            W_lin, b_lin, out);
}